// round 5
// baseline (speedup 1.0000x reference)
#include <cuda_runtime.h>
#include <cuda_fp16.h>
#include <cstdint>

#define M_DIM 4096
#define N_DIM 4096
#define K_DIM 4096

// Scratch (__device__ globals: allocation-free rule)
__device__ __half g_fqw[(size_t)N_DIM * K_DIM];   // fake-quantized W, fp16
__device__ __half g_xh [(size_t)M_DIM * K_DIM];   // x, fp16

// ---------------------------------------------------------------------------
// Kernel 1: Q4_K_M fake-quant. One WARP per 256-elem block, 8 elems/lane,
// fp16 output. sub-block s (32 elems) = lanes [4s, 4s+4).
// ---------------------------------------------------------------------------
__global__ void __launch_bounds__(256) dequant_kernel(const float4* __restrict__ W4)
{
    const int gw   = blockIdx.x * 8 + (threadIdx.x >> 5);
    const int lane = threadIdx.x & 31;
    const size_t b4 = (size_t)gw * 64 + lane * 2;

    float4 v0 = W4[b4];
    float4 v1 = W4[b4 + 1];

    float mn = fminf(fminf(fminf(v0.x, v0.y), fminf(v0.z, v0.w)),
                     fminf(fminf(v1.x, v1.y), fminf(v1.z, v1.w)));
    float mx = fmaxf(fmaxf(fmaxf(v0.x, v0.y), fmaxf(v0.z, v0.w)),
                     fmaxf(fmaxf(v1.x, v1.y), fmaxf(v1.z, v1.w)));
    mn = fminf(mn, __shfl_xor_sync(0xFFFFFFFFu, mn, 1));
    mn = fminf(mn, __shfl_xor_sync(0xFFFFFFFFu, mn, 2));
    mx = fmaxf(mx, __shfl_xor_sync(0xFFFFFFFFu, mx, 1));
    mx = fmaxf(mx, __shfl_xor_sync(0xFFFFFFFFu, mx, 2));
    mn = fminf(mn, 0.0f);
    mx = fmaxf(mx, 0.0f);

    float sr = __fdiv_rn(fmaxf(mx - mn, 1e-8f), 15.0f);

    float smin = sr, smax = sr;
    #pragma unroll
    for (int o = 4; o < 32; o <<= 1) {
        smin = fminf(smin, __shfl_xor_sync(0xFFFFFFFFu, smin, o));
        smax = fmaxf(smax, __shfl_xor_sync(0xFFFFFFFFu, smax, o));
    }
    const float srange = fmaxf(smax - smin, 1e-8f);
    float si = fminf(fmaxf(rintf(__fdiv_rn(sr - smin, srange) * 63.0f), 0.0f), 63.0f);
    float sq = __fdiv_rn(si, 63.0f) * srange + smin;
    float sb = fmaxf(sq, 1e-8f);
    float inv = __fdiv_rn(1.0f, sb);

    auto dq = [&](float w) -> float {
        float q = fminf(fmaxf(rintf((w - mn) * inv), 0.0f), 15.0f);
        return q * sb + mn;
    };
    __half2 h[4];
    h[0] = __floats2half2_rn(dq(v0.x), dq(v0.y));
    h[1] = __floats2half2_rn(dq(v0.z), dq(v0.w));
    h[2] = __floats2half2_rn(dq(v1.x), dq(v1.y));
    h[3] = __floats2half2_rn(dq(v1.z), dq(v1.w));
    reinterpret_cast<uint4*>(g_fqw)[(size_t)gw * 32 + lane] = *reinterpret_cast<uint4*>(h);
}

// ---------------------------------------------------------------------------
// Kernel 2: x -> fp16 (8 elems / thread, 16B stores)
// ---------------------------------------------------------------------------
__global__ void __launch_bounds__(256) convert_x_kernel(const float4* __restrict__ in)
{
    const size_t i = (size_t)blockIdx.x * blockDim.x + threadIdx.x;
    float4 a = in[i * 2];
    float4 b = in[i * 2 + 1];
    __half2 h[4];
    h[0] = __floats2half2_rn(a.x, a.y);
    h[1] = __floats2half2_rn(a.z, a.w);
    h[2] = __floats2half2_rn(b.x, b.y);
    h[3] = __floats2half2_rn(b.z, b.w);
    reinterpret_cast<uint4*>(g_xh)[i] = *reinterpret_cast<uint4*>(h);
}

// ---------------------------------------------------------------------------
// Kernel 3: fp16 GEMM  C[m,n] = sum_k X[m,k] * W[n,k] + bias[n]
// CTA tile 128x256, warp tile 64x64 (8 warps 2x4), BK=64 halves (128B rows,
// SW128 xor swizzle), 3-stage cp.async pipeline, ldmatrix, m16n8k16 HMMA.
// ---------------------------------------------------------------------------
#define BM 128
#define BN 256
#define BK 64
#define A_STG 16384                      // 128 rows * 128 B
#define B_STG 32768                      // 256 rows * 128 B
#define STAGE_BYTES (A_STG + B_STG)      // 49152
#define STAGES 3
#define SMEM_TOTAL (STAGES * STAGE_BYTES)  // 147456
#define NK (K_DIM / BK)                  // 64
#define SWZ(o) ((o) ^ (((o) >> 3) & 0x70))

__device__ __forceinline__ void cp16s(uint32_t s, const void* g)
{
    asm volatile("cp.async.cg.shared.global [%0], [%1], 16;" :: "r"(s), "l"(g));
}
#define LDSM_X4(r0, r1, r2, r3, a) \
    asm volatile("ldmatrix.sync.aligned.m8n8.x4.shared.b16 {%0,%1,%2,%3}, [%4];" \
                 : "=r"(r0), "=r"(r1), "=r"(r2), "=r"(r3) : "r"(a))

__global__ void __launch_bounds__(256, 1)
gemm_fp16_kernel(const float* __restrict__ bias, float* __restrict__ C)
{
    extern __shared__ char smem[];
    const uint32_t sbase = (uint32_t)__cvta_generic_to_shared(smem);

    const int tid  = threadIdx.x;
    const int warp = tid >> 5;
    const int lane = tid & 31;
    const int gid  = lane >> 2;
    const int tig  = lane & 3;

    // grid swizzle: GROUP_M=8 m-tiles per group
    const int GRID_N  = N_DIM / BN;     // 16
    const int GROUP_M = 8;
    const int gsz = GROUP_M * GRID_N;   // 128
    int tile  = blockIdx.x;
    int group = tile / gsz;
    int inb   = tile - group * gsz;
    int bm    = group * GROUP_M + (inb % GROUP_M);
    int bn    = inb / GROUP_M;

    const __half* Ag = g_xh  + (size_t)bm * BM * K_DIM;
    const __half* Bg = g_fqw + (size_t)bn * BN * K_DIM;

    const int wm = (warp >> 2) * 64;     // 0 / 64
    const int wn = (warp & 3)  * 64;     // 0..192

    float acc[4][8][4];
    #pragma unroll
    for (int i = 0; i < 4; i++)
        #pragma unroll
        for (int j = 0; j < 8; j++)
            #pragma unroll
            for (int r = 0; r < 4; r++) acc[i][j][r] = 0.0f;

    auto load_stage = [&](int stg, int kofs) {
        uint32_t sa = sbase + stg * STAGE_BYTES;
        uint32_t sbB = sa + A_STG;
        #pragma unroll
        for (int i = 0; i < 4; i++) {               // A: 1024 chunks
            int c   = tid + i * 256;
            int row = c >> 3;
            cp16s(sa + SWZ(row * 128 + (c & 7) * 16),
                  Ag + (size_t)row * K_DIM + kofs + (c & 7) * 8);
        }
        #pragma unroll
        for (int i = 0; i < 8; i++) {               // B: 2048 chunks
            int c   = tid + i * 256;
            int row = c >> 3;
            cp16s(sbB + SWZ(row * 128 + (c & 7) * 16),
                  Bg + (size_t)row * K_DIM + kofs + (c & 7) * 8);
        }
    };

    load_stage(0, 0);
    asm volatile("cp.async.commit_group;");
    load_stage(1, BK);
    asm volatile("cp.async.commit_group;");

    int stg = 0;
    for (int it = 0; it < NK; ++it) {
        asm volatile("cp.async.wait_group 1;");
        __syncthreads();

        // prefetch stage it+2 (buffer (stg+2)%3; freed by the sync above)
        if (it + 2 < NK) {
            int ns = stg + 2; if (ns >= STAGES) ns -= STAGES;
            load_stage(ns, (it + 2) * BK);
        }
        asm volatile("cp.async.commit_group;");

        const uint32_t aB = sbase + stg * STAGE_BYTES;
        const uint32_t bB = aB + A_STG;

        #pragma unroll
        for (int ks = 0; ks < 4; ++ks) {
            const int kb = ks * 32;
            uint32_t af[4][4], bf[8][2];
            #pragma unroll
            for (int mt = 0; mt < 4; ++mt) {
                int row = wm + mt * 16 + (lane & 15);
                uint32_t off = row * 128 + kb + ((lane >> 4) << 4);
                LDSM_X4(af[mt][0], af[mt][1], af[mt][2], af[mt][3], aB + SWZ(off));
            }
            #pragma unroll
            for (int nt2 = 0; nt2 < 4; ++nt2) {
                int nrow = wn + nt2 * 16 + (lane & 7) + ((lane & 16) >> 1);
                uint32_t off = nrow * 128 + kb + ((lane & 8) << 1);
                uint32_t r0, r1, r2, r3;
                LDSM_X4(r0, r1, r2, r3, bB + SWZ(off));
                bf[nt2 * 2][0]     = r0; bf[nt2 * 2][1]     = r1;
                bf[nt2 * 2 + 1][0] = r2; bf[nt2 * 2 + 1][1] = r3;
            }
            #pragma unroll
            for (int mt = 0; mt < 4; ++mt)
                #pragma unroll
                for (int nt = 0; nt < 8; ++nt) {
                    asm volatile(
                        "mma.sync.aligned.m16n8k16.row.col.f32.f16.f16.f32 "
                        "{%0,%1,%2,%3}, {%4,%5,%6,%7}, {%8,%9}, {%0,%1,%2,%3};"
                        : "+f"(acc[mt][nt][0]), "+f"(acc[mt][nt][1]),
                          "+f"(acc[mt][nt][2]), "+f"(acc[mt][nt][3])
                        : "r"(af[mt][0]), "r"(af[mt][1]), "r"(af[mt][2]), "r"(af[mt][3]),
                          "r"(bf[nt][0]), "r"(bf[nt][1]));
                }
        }
        __syncthreads();
        if (++stg >= STAGES) stg = 0;
    }

    // epilogue: bias add, fp32 stores
    #pragma unroll
    for (int nt = 0; nt < 8; ++nt) {
        int n = bn * BN + wn + nt * 8 + tig * 2;
        float b0 = bias[n], b1 = bias[n + 1];
        #pragma unroll
        for (int mt = 0; mt < 4; ++mt) {
            int m = bm * BM + wm + mt * 16 + gid;
            float2 v0 = make_float2(acc[mt][nt][0] + b0, acc[mt][nt][1] + b1);
            float2 v1 = make_float2(acc[mt][nt][2] + b0, acc[mt][nt][3] + b1);
            *reinterpret_cast<float2*>(C + (size_t)m       * N_DIM + n) = v0;
            *reinterpret_cast<float2*>(C + (size_t)(m + 8) * N_DIM + n) = v1;
        }
    }
}

// ---------------------------------------------------------------------------
extern "C" void kernel_launch(void* const* d_in, const int* in_sizes, int n_in,
                              void* d_out, int out_size)
{
    const float* x    = (const float*)d_in[0];
    const float* w    = (const float*)d_in[1];
    const float* bias = (const float*)d_in[2];
    float* out = (float*)d_out;

    dequant_kernel<<<8192, 256>>>((const float4*)w);
    convert_x_kernel<<<(M_DIM * K_DIM / 8) / 256, 256>>>((const float4*)x);

    cudaFuncSetAttribute(gemm_fp16_kernel,
                         cudaFuncAttributeMaxDynamicSharedMemorySize, SMEM_TOTAL);
    const int grid = (M_DIM / BM) * (N_DIM / BN);  // 512
    gemm_fp16_kernel<<<grid, 256, SMEM_TOTAL>>>(bias, out);
}

// round 6
// speedup vs baseline: 1.8034x; 1.8034x over previous
#include <cuda_runtime.h>
#include <cuda_fp16.h>
#include <cstdint>

#define M_DIM 4096
#define N_DIM 4096
#define K_DIM 4096

// Scratch (__device__ globals: allocation-free rule)
__device__ __half g_fqw[(size_t)N_DIM * K_DIM];   // fake-quantized W, fp16
__device__ __half g_xh [(size_t)M_DIM * K_DIM];   // x, fp16

// ---------------------------------------------------------------------------
// Fused preprocess kernel.
//   even blocks: Q4_K_M fake-quant of W (1 warp per 256-elem block, ALU-bound)
//   odd  blocks: x -> fp16 convert (pure streaming, DRAM-bound)
// Interleaving block types overlaps the ALU pipe of dequant with the memory
// pipe of convert on every SM.
// ---------------------------------------------------------------------------
__global__ void __launch_bounds__(256)
preprocess_kernel(const float4* __restrict__ W4, const float4* __restrict__ X4)
{
    const int bid = blockIdx.x;
    if (bid & 1) {
        // ---- convert x: block handles 2048 fp32 (8 per thread) ----
        const size_t i = (size_t)(bid >> 1) * 256 + threadIdx.x;
        float4 a = X4[i * 2];
        float4 b = X4[i * 2 + 1];
        __half2 h[4];
        h[0] = __floats2half2_rn(a.x, a.y);
        h[1] = __floats2half2_rn(a.z, a.w);
        h[2] = __floats2half2_rn(b.x, b.y);
        h[3] = __floats2half2_rn(b.z, b.w);
        reinterpret_cast<uint4*>(g_xh)[i] = *reinterpret_cast<uint4*>(h);
        return;
    }

    // ---- dequant W: 8 warps/CTA, one warp per 256-elem Q4_K block ----
    const int gw   = (bid >> 1) * 8 + (threadIdx.x >> 5);
    const int lane = threadIdx.x & 31;
    const size_t b4 = (size_t)gw * 64 + lane * 2;

    float4 v0 = W4[b4];
    float4 v1 = W4[b4 + 1];

    float mn = fminf(fminf(fminf(v0.x, v0.y), fminf(v0.z, v0.w)),
                     fminf(fminf(v1.x, v1.y), fminf(v1.z, v1.w)));
    float mx = fmaxf(fmaxf(fmaxf(v0.x, v0.y), fmaxf(v0.z, v0.w)),
                     fmaxf(fmaxf(v1.x, v1.y), fmaxf(v1.z, v1.w)));
    mn = fminf(mn, __shfl_xor_sync(0xFFFFFFFFu, mn, 1));
    mn = fminf(mn, __shfl_xor_sync(0xFFFFFFFFu, mn, 2));
    mx = fmaxf(mx, __shfl_xor_sync(0xFFFFFFFFu, mx, 1));
    mx = fmaxf(mx, __shfl_xor_sync(0xFFFFFFFFu, mx, 2));
    mn = fminf(mn, 0.0f);
    mx = fmaxf(mx, 0.0f);

    float sr = __fdiv_rn(fmaxf(mx - mn, 1e-8f), 15.0f);

    // 6-bit quant of the 8 sub-scales (warp-wide reduction; uniform per group)
    float smin = sr, smax = sr;
    #pragma unroll
    for (int o = 4; o < 32; o <<= 1) {
        smin = fminf(smin, __shfl_xor_sync(0xFFFFFFFFu, smin, o));
        smax = fmaxf(smax, __shfl_xor_sync(0xFFFFFFFFu, smax, o));
    }
    const float srange = fmaxf(smax - smin, 1e-8f);
    float si = fminf(fmaxf(rintf(__fdiv_rn(sr - smin, srange) * 63.0f), 0.0f), 63.0f);
    float sq = __fdiv_rn(si, 63.0f) * srange + smin;
    float sb = fmaxf(sq, 1e-8f);
    float inv = __fdiv_rn(1.0f, sb);

    auto dq = [&](float w) -> float {
        float q = fminf(fmaxf(rintf((w - mn) * inv), 0.0f), 15.0f);
        return q * sb + mn;
    };
    __half2 h[4];
    h[0] = __floats2half2_rn(dq(v0.x), dq(v0.y));
    h[1] = __floats2half2_rn(dq(v0.z), dq(v0.w));
    h[2] = __floats2half2_rn(dq(v1.x), dq(v1.y));
    h[3] = __floats2half2_rn(dq(v1.z), dq(v1.w));
    reinterpret_cast<uint4*>(g_fqw)[(size_t)gw * 32 + lane] = *reinterpret_cast<uint4*>(h);
}

// ---------------------------------------------------------------------------
// fp16 GEMM  C[m,n] = sum_k X[m,k] * W[n,k] + bias[n]      (round-4 config)
// 128x128 CTA tile, BK=64 halves (128B rows, SW128 xor swizzle),
// double-buffered cp.async, ldmatrix fragments, m16n8k16 HMMA, fp32 accum,
// 2 CTAs/SM.
// ---------------------------------------------------------------------------
#define BM 128
#define BN 128
#define BK 64
#define STAGE_BYTES 32768               // 16KB A + 16KB B
#define SMEM_TOTAL (2 * STAGE_BYTES)    // 65536
#define NK (K_DIM / BK)                 // 64
#define SWZ(o) ((o) ^ (((o) >> 3) & 0x70))

__device__ __forceinline__ void cp16s(uint32_t s, const void* g)
{
    asm volatile("cp.async.cg.shared.global [%0], [%1], 16;" :: "r"(s), "l"(g));
}
#define LDSM_X4(r0, r1, r2, r3, a) \
    asm volatile("ldmatrix.sync.aligned.m8n8.x4.shared.b16 {%0,%1,%2,%3}, [%4];" \
                 : "=r"(r0), "=r"(r1), "=r"(r2), "=r"(r3) : "r"(a))

__global__ void __launch_bounds__(256, 2)
gemm_fp16_kernel(const float* __restrict__ bias, float* __restrict__ C)
{
    extern __shared__ char smem[];
    const uint32_t sbase = (uint32_t)__cvta_generic_to_shared(smem);

    const int tid  = threadIdx.x;
    const int warp = tid >> 5;
    const int lane = tid & 31;
    const int gid  = lane >> 2;
    const int tig  = lane & 3;

    // grid swizzle: GROUP_M=8 m-tiles per group for L2 reuse
    const int GRID_N  = N_DIM / BN;     // 32
    const int GROUP_M = 8;
    const int gsz = GROUP_M * GRID_N;   // 256
    int tile  = blockIdx.x;
    int group = tile / gsz;
    int inb   = tile - group * gsz;
    int bm    = group * GROUP_M + (inb % GROUP_M);
    int bn    = inb / GROUP_M;

    const __half* Ag = g_xh  + (size_t)bm * BM * K_DIM;
    const __half* Bg = g_fqw + (size_t)bn * BN * K_DIM;

    const int wm = (warp >> 2) * 64;
    const int wn = (warp & 3)  * 32;

    float acc[4][4][4];
    #pragma unroll
    for (int i = 0; i < 4; i++)
        #pragma unroll
        for (int j = 0; j < 4; j++)
            #pragma unroll
            for (int r = 0; r < 4; r++) acc[i][j][r] = 0.0f;

    auto load_tile = [&](const __half* __restrict__ g, uint32_t sdst, int kofs) {
        #pragma unroll
        for (int i = 0; i < 4; i++) {
            int c   = tid + i * 256;          // 1024 chunks of 16B
            int row = c >> 3;
            int kc  = (c & 7) * 8;            // halves
            cp16s(sdst + SWZ(row * 128 + (c & 7) * 16),
                  g + (size_t)row * K_DIM + kofs + kc);
        }
    };

    load_tile(Ag, sbase, 0);
    load_tile(Bg, sbase + 16384, 0);
    asm volatile("cp.async.commit_group;");

    for (int it = 0; it < NK; ++it) {
        const int cur = it & 1;
        if (it + 1 < NK) {
            uint32_t nb = sbase + (cur ^ 1) * STAGE_BYTES;
            load_tile(Ag, nb,         (it + 1) * BK);
            load_tile(Bg, nb + 16384, (it + 1) * BK);
            asm volatile("cp.async.commit_group;");
            asm volatile("cp.async.wait_group 1;");
        } else {
            asm volatile("cp.async.wait_group 0;");
        }
        __syncthreads();

        const uint32_t aB = sbase + cur * STAGE_BYTES;
        const uint32_t bB = aB + 16384;

        #pragma unroll
        for (int ks = 0; ks < 4; ++ks) {
            const int kb = ks * 32;           // byte offset of k0 = ks*16 halves
            uint32_t af[4][4], bf[4][2];
            #pragma unroll
            for (int mt = 0; mt < 4; ++mt) {
                int row = wm + mt * 16 + (lane & 15);
                uint32_t off = row * 128 + kb + ((lane >> 4) << 4);
                LDSM_X4(af[mt][0], af[mt][1], af[mt][2], af[mt][3], aB + SWZ(off));
            }
            #pragma unroll
            for (int nt2 = 0; nt2 < 2; ++nt2) {
                int nrow = wn + nt2 * 16 + (lane & 7) + ((lane & 16) >> 1);
                uint32_t off = nrow * 128 + kb + ((lane & 8) << 1);
                uint32_t r0, r1, r2, r3;
                LDSM_X4(r0, r1, r2, r3, bB + SWZ(off));
                bf[nt2 * 2][0]     = r0; bf[nt2 * 2][1]     = r1;
                bf[nt2 * 2 + 1][0] = r2; bf[nt2 * 2 + 1][1] = r3;
            }
            #pragma unroll
            for (int mt = 0; mt < 4; ++mt)
                #pragma unroll
                for (int nt = 0; nt < 4; ++nt) {
                    asm volatile(
                        "mma.sync.aligned.m16n8k16.row.col.f32.f16.f16.f32 "
                        "{%0,%1,%2,%3}, {%4,%5,%6,%7}, {%8,%9}, {%0,%1,%2,%3};"
                        : "+f"(acc[mt][nt][0]), "+f"(acc[mt][nt][1]),
                          "+f"(acc[mt][nt][2]), "+f"(acc[mt][nt][3])
                        : "r"(af[mt][0]), "r"(af[mt][1]), "r"(af[mt][2]), "r"(af[mt][3]),
                          "r"(bf[nt][0]), "r"(bf[nt][1]));
                }
        }
        __syncthreads();
    }

    // epilogue: bias add, fp32 stores
    #pragma unroll
    for (int nt = 0; nt < 4; ++nt) {
        int n = bn * BN + wn + nt * 8 + tig * 2;
        float b0 = bias[n], b1 = bias[n + 1];
        #pragma unroll
        for (int mt = 0; mt < 4; ++mt) {
            int m = bm * BM + wm + mt * 16 + gid;
            float2 v0 = make_float2(acc[mt][nt][0] + b0, acc[mt][nt][1] + b1);
            float2 v1 = make_float2(acc[mt][nt][2] + b0, acc[mt][nt][3] + b1);
            *reinterpret_cast<float2*>(C + (size_t)m       * N_DIM + n) = v0;
            *reinterpret_cast<float2*>(C + (size_t)(m + 8) * N_DIM + n) = v1;
        }
    }
}

// ---------------------------------------------------------------------------
extern "C" void kernel_launch(void* const* d_in, const int* in_sizes, int n_in,
                              void* d_out, int out_size)
{
    const float* x    = (const float*)d_in[0];
    const float* w    = (const float*)d_in[1];
    const float* bias = (const float*)d_in[2];
    float* out = (float*)d_out;

    // fused preprocess: 8192 dequant blocks (even) + 8192 convert blocks (odd)
    preprocess_kernel<<<16384, 256>>>((const float4*)w, (const float4*)x);

    cudaFuncSetAttribute(gemm_fp16_kernel,
                         cudaFuncAttributeMaxDynamicSharedMemorySize, SMEM_TOTAL);
    const int grid = (M_DIM / BM) * (N_DIM / BN);  // 1024
    gemm_fp16_kernel<<<grid, 256, SMEM_TOTAL>>>(bias, out);
}

// round 7
// speedup vs baseline: 1.8776x; 1.0411x over previous
#include <cuda_runtime.h>
#include <cuda_fp16.h>
#include <cstdint>

#define M_DIM 4096
#define N_DIM 4096
#define K_DIM 4096

// Scratch (__device__ globals: allocation-free rule)
__device__ __half g_fqw[(size_t)N_DIM * K_DIM];   // fake-quantized W, fp16
__device__ __half g_xh [(size_t)M_DIM * K_DIM];   // x, fp16

// ---------------------------------------------------------------------------
// Fused preprocess kernel (proven round 6).
//   even blocks: Q4_K_M fake-quant of W (1 warp per 256-elem block, ALU-bound)
//   odd  blocks: x -> fp16 convert (pure streaming, DRAM-bound)
// ---------------------------------------------------------------------------
__global__ void __launch_bounds__(256)
preprocess_kernel(const float4* __restrict__ W4, const float4* __restrict__ X4)
{
    const int bid = blockIdx.x;
    if (bid & 1) {
        const size_t i = (size_t)(bid >> 1) * 256 + threadIdx.x;
        float4 a = X4[i * 2];
        float4 b = X4[i * 2 + 1];
        __half2 h[4];
        h[0] = __floats2half2_rn(a.x, a.y);
        h[1] = __floats2half2_rn(a.z, a.w);
        h[2] = __floats2half2_rn(b.x, b.y);
        h[3] = __floats2half2_rn(b.z, b.w);
        reinterpret_cast<uint4*>(g_xh)[i] = *reinterpret_cast<uint4*>(h);
        return;
    }

    const int gw   = (bid >> 1) * 8 + (threadIdx.x >> 5);
    const int lane = threadIdx.x & 31;
    const size_t b4 = (size_t)gw * 64 + lane * 2;

    float4 v0 = W4[b4];
    float4 v1 = W4[b4 + 1];

    float mn = fminf(fminf(fminf(v0.x, v0.y), fminf(v0.z, v0.w)),
                     fminf(fminf(v1.x, v1.y), fminf(v1.z, v1.w)));
    float mx = fmaxf(fmaxf(fmaxf(v0.x, v0.y), fmaxf(v0.z, v0.w)),
                     fmaxf(fmaxf(v1.x, v1.y), fmaxf(v1.z, v1.w)));
    mn = fminf(mn, __shfl_xor_sync(0xFFFFFFFFu, mn, 1));
    mn = fminf(mn, __shfl_xor_sync(0xFFFFFFFFu, mn, 2));
    mx = fmaxf(mx, __shfl_xor_sync(0xFFFFFFFFu, mx, 1));
    mx = fmaxf(mx, __shfl_xor_sync(0xFFFFFFFFu, mx, 2));
    mn = fminf(mn, 0.0f);
    mx = fmaxf(mx, 0.0f);

    float sr = __fdiv_rn(fmaxf(mx - mn, 1e-8f), 15.0f);

    float smin = sr, smax = sr;
    #pragma unroll
    for (int o = 4; o < 32; o <<= 1) {
        smin = fminf(smin, __shfl_xor_sync(0xFFFFFFFFu, smin, o));
        smax = fmaxf(smax, __shfl_xor_sync(0xFFFFFFFFu, smax, o));
    }
    const float srange = fmaxf(smax - smin, 1e-8f);
    float si = fminf(fmaxf(rintf(__fdiv_rn(sr - smin, srange) * 63.0f), 0.0f), 63.0f);
    float sq = __fdiv_rn(si, 63.0f) * srange + smin;
    float sb = fmaxf(sq, 1e-8f);
    float inv = __fdiv_rn(1.0f, sb);

    auto dq = [&](float w) -> float {
        float q = fminf(fmaxf(rintf((w - mn) * inv), 0.0f), 15.0f);
        return q * sb + mn;
    };
    __half2 h[4];
    h[0] = __floats2half2_rn(dq(v0.x), dq(v0.y));
    h[1] = __floats2half2_rn(dq(v0.z), dq(v0.w));
    h[2] = __floats2half2_rn(dq(v1.x), dq(v1.y));
    h[3] = __floats2half2_rn(dq(v1.z), dq(v1.w));
    reinterpret_cast<uint4*>(g_fqw)[(size_t)gw * 32 + lane] = *reinterpret_cast<uint4*>(h);
}

// ---------------------------------------------------------------------------
// fp16 GEMM  C[m,n] = sum_k X[m,k] * W[n,k] + bias[n]
// 128x128 CTA tile, BK=64, SW128 swizzle, 3-stage cp.async pipeline with a
// SINGLE __syncthreads per iteration, ldmatrix, m16n8k16 HMMA, 2 CTAs/SM.
// ---------------------------------------------------------------------------
#define BM 128
#define BN 128
#define BK 64
#define STAGE_BYTES 32768               // 16KB A + 16KB B
#define STAGES 3
#define SMEM_TOTAL (STAGES * STAGE_BYTES)  // 98304; 2 CTAs = 192KB <= 228KB
#define NK (K_DIM / BK)                 // 64
#define SWZ(o) ((o) ^ (((o) >> 3) & 0x70))

__device__ __forceinline__ void cp16s(uint32_t s, const void* g)
{
    asm volatile("cp.async.cg.shared.global [%0], [%1], 16;" :: "r"(s), "l"(g));
}
#define LDSM_X4(r0, r1, r2, r3, a) \
    asm volatile("ldmatrix.sync.aligned.m8n8.x4.shared.b16 {%0,%1,%2,%3}, [%4];" \
                 : "=r"(r0), "=r"(r1), "=r"(r2), "=r"(r3) : "r"(a))

__global__ void __launch_bounds__(256, 2)
gemm_fp16_kernel(const float* __restrict__ bias, float* __restrict__ C)
{
    extern __shared__ char smem[];
    const uint32_t sbase = (uint32_t)__cvta_generic_to_shared(smem);

    const int tid  = threadIdx.x;
    const int warp = tid >> 5;
    const int lane = tid & 31;
    const int gid  = lane >> 2;
    const int tig  = lane & 3;

    // grid swizzle: GROUP_M=8 m-tiles per group for L2 reuse
    const int GRID_N  = N_DIM / BN;     // 32
    const int GROUP_M = 8;
    const int gsz = GROUP_M * GRID_N;   // 256
    int tile  = blockIdx.x;
    int group = tile / gsz;
    int inb   = tile - group * gsz;
    int bm    = group * GROUP_M + (inb % GROUP_M);
    int bn    = inb / GROUP_M;

    const __half* Ag = g_xh  + (size_t)bm * BM * K_DIM;
    const __half* Bg = g_fqw + (size_t)bn * BN * K_DIM;

    const int wm = (warp >> 2) * 64;
    const int wn = (warp & 3)  * 32;

    float acc[4][4][4];
    #pragma unroll
    for (int i = 0; i < 4; i++)
        #pragma unroll
        for (int j = 0; j < 4; j++)
            #pragma unroll
            for (int r = 0; r < 4; r++) acc[i][j][r] = 0.0f;

    auto load_stage = [&](int stg, int kofs) {
        uint32_t sa = sbase + stg * STAGE_BYTES;
        #pragma unroll
        for (int i = 0; i < 4; i++) {            // A: 1024 chunks of 16B
            int c   = tid + i * 256;
            int row = c >> 3;
            cp16s(sa + SWZ(row * 128 + (c & 7) * 16),
                  Ag + (size_t)row * K_DIM + kofs + (c & 7) * 8);
        }
        uint32_t sB = sa + 16384;
        #pragma unroll
        for (int i = 0; i < 4; i++) {            // B: 1024 chunks
            int c   = tid + i * 256;
            int row = c >> 3;
            cp16s(sB + SWZ(row * 128 + (c & 7) * 16),
                  Bg + (size_t)row * K_DIM + kofs + (c & 7) * 8);
        }
    };

    load_stage(0, 0);
    asm volatile("cp.async.commit_group;");
    load_stage(1, BK);
    asm volatile("cp.async.commit_group;");

    int stg = 0;
    for (int it = 0; it < NK; ++it) {
        asm volatile("cp.async.wait_group 1;");
        __syncthreads();
        // loads for it+2 target the stage read at it-1 (safe past the barrier)
        if (it + 2 < NK) {
            int ns = stg + 2; if (ns >= STAGES) ns -= STAGES;
            load_stage(ns, (it + 2) * BK);
        }
        asm volatile("cp.async.commit_group;");

        const uint32_t aB = sbase + stg * STAGE_BYTES;
        const uint32_t bB = aB + 16384;

        #pragma unroll
        for (int ks = 0; ks < 4; ++ks) {
            const int kb = ks * 32;
            uint32_t af[4][4], bf[4][2];
            #pragma unroll
            for (int mt = 0; mt < 4; ++mt) {
                int row = wm + mt * 16 + (lane & 15);
                uint32_t off = row * 128 + kb + ((lane >> 4) << 4);
                LDSM_X4(af[mt][0], af[mt][1], af[mt][2], af[mt][3], aB + SWZ(off));
            }
            #pragma unroll
            for (int nt2 = 0; nt2 < 2; ++nt2) {
                int nrow = wn + nt2 * 16 + (lane & 7) + ((lane & 16) >> 1);
                uint32_t off = nrow * 128 + kb + ((lane & 8) << 1);
                uint32_t r0, r1, r2, r3;
                LDSM_X4(r0, r1, r2, r3, bB + SWZ(off));
                bf[nt2 * 2][0]     = r0; bf[nt2 * 2][1]     = r1;
                bf[nt2 * 2 + 1][0] = r2; bf[nt2 * 2 + 1][1] = r3;
            }
            #pragma unroll
            for (int mt = 0; mt < 4; ++mt)
                #pragma unroll
                for (int nt = 0; nt < 4; ++nt) {
                    asm volatile(
                        "mma.sync.aligned.m16n8k16.row.col.f32.f16.f16.f32 "
                        "{%0,%1,%2,%3}, {%4,%5,%6,%7}, {%8,%9}, {%0,%1,%2,%3};"
                        : "+f"(acc[mt][nt][0]), "+f"(acc[mt][nt][1]),
                          "+f"(acc[mt][nt][2]), "+f"(acc[mt][nt][3])
                        : "r"(af[mt][0]), "r"(af[mt][1]), "r"(af[mt][2]), "r"(af[mt][3]),
                          "r"(bf[nt][0]), "r"(bf[nt][1]));
                }
        }
        if (++stg >= STAGES) stg = 0;
    }

    // epilogue: bias add, fp32 stores
    #pragma unroll
    for (int nt = 0; nt < 4; ++nt) {
        int n = bn * BN + wn + nt * 8 + tig * 2;
        float b0 = bias[n], b1 = bias[n + 1];
        #pragma unroll
        for (int mt = 0; mt < 4; ++mt) {
            int m = bm * BM + wm + mt * 16 + gid;
            float2 v0 = make_float2(acc[mt][nt][0] + b0, acc[mt][nt][1] + b1);
            float2 v1 = make_float2(acc[mt][nt][2] + b0, acc[mt][nt][3] + b1);
            *reinterpret_cast<float2*>(C + (size_t)m       * N_DIM + n) = v0;
            *reinterpret_cast<float2*>(C + (size_t)(m + 8) * N_DIM + n) = v1;
        }
    }
}

// ---------------------------------------------------------------------------
extern "C" void kernel_launch(void* const* d_in, const int* in_sizes, int n_in,
                              void* d_out, int out_size)
{
    const float* x    = (const float*)d_in[0];
    const float* w    = (const float*)d_in[1];
    const float* bias = (const float*)d_in[2];
    float* out = (float*)d_out;

    // fused preprocess: 8192 dequant blocks (even) + 8192 convert blocks (odd)
    preprocess_kernel<<<16384, 256>>>((const float4*)w, (const float4*)x);

    cudaFuncSetAttribute(gemm_fp16_kernel,
                         cudaFuncAttributeMaxDynamicSharedMemorySize, SMEM_TOTAL);
    const int grid = (M_DIM / BM) * (N_DIM / BN);  // 1024
    gemm_fp16_kernel<<<grid, 256, SMEM_TOTAL>>>(bias, out);
}